// round 4
// baseline (speedup 1.0000x reference)
#include <cuda_runtime.h>
#include <cuda_bf16.h>
#include <cstdint>

// ============================================================================
// Problem constants
// ============================================================================
#define NROWS 16384
#define DDIM  128
#define TILE  128

// fp8 e4m3 operands, scaled by 8 per vector (dot scales by 64)
static __device__ uint8_t g_Aq[NROWS * DDIM];
static __device__ uint8_t g_Pq[NROWS * DDIM];
static __device__ float g_partS[4 * NROWS];   // per-row expsum partials
static __device__ float g_diagv[NROWS];       // scaled diag (64*dot)
static __device__ float g_acc;

#define QSCALE  8.0f
// exp2 epilogue constant: (log2e / T) / 64
#define C_EPI   0.32203014305557220f
// diag constant: (1/T) / 64
#define DIAG_C  0.22321428571428571f

// SMEM: A slab @0, three B buffers. fp8 tile = 128 rows x 128B, padded to 144B.
#define ROWB   144
#define SLAB   18432
#define SMEM_TOTAL (4 * 18432)

// ============================================================================
// PTX helpers (sm_80/89+ portable; ptxas target is plain sm_100 -> no tcgen05)
// ============================================================================
__device__ __forceinline__ uint32_t smem_to_u32(const void* p) {
    uint32_t a;
    asm("{ .reg .u64 t; cvta.to.shared.u64 t, %1; cvt.u32.u64 %0, t; }" : "=r"(a) : "l"(p));
    return a;
}
__device__ __forceinline__ float ex2f_fast(float x) {
    float y; asm("ex2.approx.ftz.f32 %0, %1;" : "=f"(y) : "f"(x)); return y;
}
// pack 4 floats (v0 = lowest byte) -> 4x e4m3
__device__ __forceinline__ uint32_t pack4_e4m3(float v0, float v1, float v2, float v3) {
    uint16_t lo, hi;
    asm("cvt.rn.satfinite.e4m3x2.f32 %0, %1, %2;" : "=h"(lo) : "f"(v1), "f"(v0));
    asm("cvt.rn.satfinite.e4m3x2.f32 %0, %1, %2;" : "=h"(hi) : "f"(v3), "f"(v2));
    return (uint32_t)lo | ((uint32_t)hi << 16);
}

#define LDSM_X4(r0, r1, r2, r3, addr) \
    asm volatile("ldmatrix.sync.aligned.m8n8.x4.shared.b16 {%0,%1,%2,%3}, [%4];" \
        : "=r"(r0), "=r"(r1), "=r"(r2), "=r"(r3) : "r"(addr))

#define MMA_FP8(d, a, b0, b1) \
    asm volatile("mma.sync.aligned.m16n8k32.row.col.f32.e4m3.e4m3.f32 " \
        "{%0,%1,%2,%3},{%4,%5,%6,%7},{%8,%9},{%0,%1,%2,%3};" \
        : "+f"((d)[0]), "+f"((d)[1]), "+f"((d)[2]), "+f"((d)[3]) \
        : "r"((a)[0]), "r"((a)[1]), "r"((a)[2]), "r"((a)[3]), "r"(b0), "r"(b1))

#define CP_ASYNC16(saddr, gptr) \
    asm volatile("cp.async.cg.shared.global [%0], [%1], 16;" :: "r"(saddr), "l"(gptr))
#define CP_COMMIT() asm volatile("cp.async.commit_group;")
#define CP_WAIT1()  asm volatile("cp.async.wait_group 1;")
#define CP_WAIT2()  asm volatile("cp.async.wait_group 2;")

// ============================================================================
// Kernel 1: normalize rows (fp32) -> e4m3 (scaled by 8), zero accumulator
// ============================================================================
__global__ void __launch_bounds__(256) normalize_kernel(const float* __restrict__ A,
                                                        const float* __restrict__ P) {
    if (blockIdx.x == 0 && threadIdx.x == 0) g_acc = 0.0f;
    int warp = (blockIdx.x * blockDim.x + threadIdx.x) >> 5;
    int lane = threadIdx.x & 31;
    if (warp >= 2 * NROWS) return;
    const float* src;
    uint8_t* dst;
    if (warp < NROWS) { src = A + (size_t)warp * DDIM; dst = g_Aq + (size_t)warp * DDIM; }
    else { int r = warp - NROWS; src = P + (size_t)r * DDIM; dst = g_Pq + (size_t)r * DDIM; }
    float4 v = reinterpret_cast<const float4*>(src)[lane];
    float ss = v.x * v.x + v.y * v.y + v.z * v.z + v.w * v.w;
    #pragma unroll
    for (int o = 16; o > 0; o >>= 1) ss += __shfl_xor_sync(0xFFFFFFFFu, ss, o);
    float s = QSCALE / fmaxf(sqrtf(ss), 1e-12f);
    reinterpret_cast<uint32_t*>(dst)[lane] =
        pack4_e4m3(v.x * s, v.y * s, v.z * s, v.w * s);
}

// ============================================================================
// cp.async loader: 128x128 fp8 tile (row-major) -> padded SMEM (144B rows)
// ============================================================================
__device__ __forceinline__ void cp_tile(uint32_t sbase, const uint8_t* gsrc, int tid) {
    const char* g = reinterpret_cast<const char*>(gsrc);
    #pragma unroll
    for (int i = 0; i < 4; i++) {
        int idx = tid + i * 256;          // 1024 chunks of 16B
        int row = idx >> 3;               // 8 chunks per 128-byte row
        int c   = idx & 7;
        uint32_t s = sbase + row * ROWB + c * 16;
        CP_ASYNC16(s, g + idx * 16);
    }
}

// ============================================================================
// Kernel 2: fused fp8 GEMM + exp rowsum + diag.
// grid = (128 row-blocks, 2 column halves), 256 threads.
// Warp (wr, wc): 32 rows x 64 cols per warp. A frags register-resident.
// 3-buffer cp.async pipeline, one __syncthreads per tile.
// ============================================================================
__global__ void __launch_bounds__(256, 2) infonce_main_kernel() {
    extern __shared__ char smem[];
    uint32_t sb = smem_to_u32(smem);
    int tid = threadIdx.x;
    int lane = tid & 31;
    int w = tid >> 5;
    int wr = w >> 1;            // row-group 0..3
    int wc = w & 1;             // col-group 0..1
    int rb = blockIdx.x;        // row block
    int ch = blockIdx.y;        // column half
    int gt0 = ch * 64;

    const uint32_t bufoff[3] = {SLAB, 2 * SLAB, 3 * SLAB};

    // Prologue: A tile -> @0; B tiles t0 -> buf0, t1 -> buf1
    cp_tile(sb + 0, g_Aq + (size_t)rb * TILE * DDIM, tid);
    CP_COMMIT();
    cp_tile(sb + bufoff[0], g_Pq + (size_t)gt0 * TILE * DDIM, tid);
    CP_COMMIT();
    cp_tile(sb + bufoff[1], g_Pq + (size_t)(gt0 + 1) * TILE * DDIM, tid);
    CP_COMMIT();
    CP_WAIT2();                  // A done
    __syncthreads();

    // A fragments: 4 k-steps (k32 each) x 2 m16-frags x 4 regs = 32 regs
    uint32_t afrag[4][2][4];
    #pragma unroll
    for (int f = 0; f < 2; f++) {
        uint32_t a_addr = sb + (wr * 32 + f * 16 + (lane & 15)) * ROWB + (lane >> 4) * 16;
        #pragma unroll
        for (int k = 0; k < 4; k++)
            LDSM_X4(afrag[k][f][0], afrag[k][f][1], afrag[k][f][2], afrag[k][f][3],
                    a_addr + k * 32);
    }

    int g = lane >> 2;
    int tig = lane & 3;
    uint32_t b_lane_off = (uint32_t)(((lane & 7) + ((lane >> 4) << 3)) * ROWB
                                     + ((lane >> 3) & 1) * 16)
                          + (uint32_t)(wc * 64) * ROWB;

    float S[4] = {0.f, 0.f, 0.f, 0.f};
    float d[4] = {0.f, 0.f, 0.f, 0.f};

    int curbuf = 0, nxtbuf = 2;

    for (int t = 0; t < 64; t++) {
        CP_WAIT1();
        __syncthreads();
        if (t + 2 < 64)
            cp_tile(sb + bufoff[nxtbuf], g_Pq + (size_t)(gt0 + t + 2) * TILE * DDIM, tid);
        CP_COMMIT();

        uint32_t bbase = sb + bufoff[curbuf] + b_lane_off;
        int diag_t = (gt0 + t == rb);

        #pragma unroll
        for (int c = 0; c < 4; c++) {
            float acc[2][2][4];
            #pragma unroll
            for (int f = 0; f < 2; f++)
                #pragma unroll
                for (int nb = 0; nb < 2; nb++)
                    #pragma unroll
                    for (int j = 0; j < 4; j++) acc[f][nb][j] = 0.0f;

            uint32_t bchunk = bbase + (uint32_t)(c * 16) * ROWB;
            #pragma unroll
            for (int k = 0; k < 4; k++) {
                uint32_t b0, b1, b2, b3;
                // b0,b1 = nblock0 (k bytes 0-15 / 16-31); b2,b3 = nblock1
                LDSM_X4(b0, b1, b2, b3, bchunk + k * 32);
                MMA_FP8(acc[0][0], afrag[k][0], b0, b1);
                MMA_FP8(acc[0][1], afrag[k][0], b2, b3);
                MMA_FP8(acc[1][0], afrag[k][1], b0, b1);
                MMA_FP8(acc[1][1], afrag[k][1], b2, b3);
            }
            // epilogue: exp2(acc * C_EPI) + running row sums (+ diag capture)
            #pragma unroll
            for (int f = 0; f < 2; f++) {
                #pragma unroll
                for (int nb = 0; nb < 2; nb++) {
                    #pragma unroll
                    for (int j = 0; j < 4; j++) {
                        float v = acc[f][nb][j];
                        int hi = j >> 1;
                        S[f * 2 + hi] += ex2f_fast(v * C_EPI);
                        if (diag_t) {
                            int col_local = wc * 64 + c * 16 + nb * 8 + tig * 2 + (j & 1);
                            int row_local = wr * 32 + f * 16 + hi * 8 + g;
                            if (col_local == row_local) d[f * 2 + hi] = v;
                        }
                    }
                }
            }
        }
        if (++curbuf == 3) curbuf = 0;
        if (++nxtbuf == 3) nxtbuf = 0;
    }

    // reduce across the 4 threads sharing each row
    #pragma unroll
    for (int i = 0; i < 4; i++) {
        S[i] += __shfl_xor_sync(0xFFFFFFFFu, S[i], 1);
        S[i] += __shfl_xor_sync(0xFFFFFFFFu, S[i], 2);
        d[i] += __shfl_xor_sync(0xFFFFFFFFu, d[i], 1);
        d[i] += __shfl_xor_sync(0xFFFFFFFFu, d[i], 2);
    }

    if (tig == 0) {
        int part = ch * 2 + wc;
        int wrote_diag = (ch == (rb >> 6)) && ((wr >> 1) == wc);
        #pragma unroll
        for (int i = 0; i < 4; i++) {
            int row_local = wr * 32 + (i >> 1) * 16 + (i & 1) * 8 + g;
            int row = rb * TILE + row_local;
            g_partS[part * NROWS + row] = S[i];
            if (wrote_diag) g_diagv[row] = d[i];
        }
    }
}

// ============================================================================
// Kernel 3: per-row loss + global reduction
// ============================================================================
__global__ void __launch_bounds__(256) rowsum_kernel() {
    int row = blockIdx.x * 256 + threadIdx.x;
    float Ssum = g_partS[row] + g_partS[NROWS + row]
               + g_partS[2 * NROWS + row] + g_partS[3 * NROWS + row];
    float v = logf(Ssum) - g_diagv[row] * DIAG_C;
    #pragma unroll
    for (int o = 16; o > 0; o >>= 1) v += __shfl_xor_sync(0xFFFFFFFFu, v, o);
    __shared__ float red[8];
    int lane = threadIdx.x & 31, wid = threadIdx.x >> 5;
    if (lane == 0) red[wid] = v;
    __syncthreads();
    if (wid == 0) {
        float s = (lane < 8) ? red[lane] : 0.0f;
        #pragma unroll
        for (int o = 4; o > 0; o >>= 1) s += __shfl_xor_sync(0xFFFFFFFFu, s, o);
        if (lane == 0) atomicAdd(&g_acc, s);
    }
}

// ============================================================================
// Kernel 4: finalize
// ============================================================================
__global__ void finalize_kernel(float* out) {
    out[0] = g_acc * (1.0f / (float)NROWS);
}

// ============================================================================
// Launch
// ============================================================================
extern "C" void kernel_launch(void* const* d_in, const int* in_sizes, int n_in,
                              void* d_out, int out_size) {
    const float* A = (const float*)d_in[0];
    const float* P = (const float*)d_in[1];
    cudaFuncSetAttribute(infonce_main_kernel,
                         cudaFuncAttributeMaxDynamicSharedMemorySize, SMEM_TOTAL);
    normalize_kernel<<<(2 * NROWS) / 8, 256>>>(A, P);
    dim3 grid(128, 2);
    infonce_main_kernel<<<grid, 256, SMEM_TOTAL>>>();
    rowsum_kernel<<<NROWS / 256, 256>>>();
    finalize_kernel<<<1, 1>>>((float*)d_out);
}

// round 5
// speedup vs baseline: 1.4433x; 1.4433x over previous
#include <cuda_runtime.h>
#include <cuda_bf16.h>
#include <cstdint>

// ============================================================================
// Problem constants
// ============================================================================
#define NROWS 16384
#define DDIM  128
#define TILE  128
#define NJOBS 16384              // 128 row-blocks x 128 col-tiles

static __device__ __nv_bfloat16 g_Abf[NROWS * DDIM];
static __device__ __nv_bfloat16 g_Pbf[NROWS * DDIM];
static __device__ float g_partS[NROWS];   // per-row expsum (atomic-accumulated)
static __device__ float g_diagv[NROWS];
static __device__ float g_acc;

#define INV_T   14.285714285714286f
#define C_EXP   20.609929155556620f   // log2(e) / 0.07

// SMEM: 3 rotating 128x128 bf16 slabs (272B padded rows). Slab @0 holds the
// A tile at segment start, then rejoins the B rotation (frags are in regs).
#define ROWB   272
#define SLAB   34816
#define SMEM_TOTAL (3 * 34816)

// ============================================================================
// PTX helpers (sm_80+ portable; ptxas target is plain sm_100 -> no tcgen05)
// ============================================================================
__device__ __forceinline__ uint32_t smem_to_u32(const void* p) {
    uint32_t a;
    asm("{ .reg .u64 t; cvta.to.shared.u64 t, %1; cvt.u32.u64 %0, t; }" : "=r"(a) : "l"(p));
    return a;
}
__device__ __forceinline__ float ex2f_fast(float x) {
    float y; asm("ex2.approx.ftz.f32 %0, %1;" : "=f"(y) : "f"(x)); return y;
}

#define LDSM_X4(r0, r1, r2, r3, addr) \
    asm volatile("ldmatrix.sync.aligned.m8n8.x4.shared.b16 {%0,%1,%2,%3}, [%4];" \
        : "=r"(r0), "=r"(r1), "=r"(r2), "=r"(r3) : "r"(addr))

#define MMA_BF16(d, a, b0, b1) \
    asm volatile("mma.sync.aligned.m16n8k16.row.col.f32.bf16.bf16.f32 " \
        "{%0,%1,%2,%3},{%4,%5,%6,%7},{%8,%9},{%0,%1,%2,%3};" \
        : "+f"((d)[0]), "+f"((d)[1]), "+f"((d)[2]), "+f"((d)[3]) \
        : "r"((a)[0]), "r"((a)[1]), "r"((a)[2]), "r"((a)[3]), "r"(b0), "r"(b1))

#define CP_ASYNC16(saddr, gptr) \
    asm volatile("cp.async.cg.shared.global [%0], [%1], 16;" :: "r"(saddr), "l"(gptr))
#define CP_COMMIT() asm volatile("cp.async.commit_group;")
#define CP_WAIT1()  asm volatile("cp.async.wait_group 1;")
#define CP_WAIT2()  asm volatile("cp.async.wait_group 2;")

// ============================================================================
// Kernel 1: normalize rows (fp32) -> bf16; zero partS + acc
// ============================================================================
__global__ void __launch_bounds__(256) normalize_kernel(const float* __restrict__ A,
                                                        const float* __restrict__ P) {
    int gid = blockIdx.x * blockDim.x + threadIdx.x;
    if (gid == 0) g_acc = 0.0f;
    if (gid < NROWS) g_partS[gid] = 0.0f;
    int warp = gid >> 5;
    int lane = threadIdx.x & 31;
    if (warp >= 2 * NROWS) return;
    const float* src;
    __nv_bfloat16* dst;
    if (warp < NROWS) { src = A + (size_t)warp * DDIM; dst = g_Abf + (size_t)warp * DDIM; }
    else { int r = warp - NROWS; src = P + (size_t)r * DDIM; dst = g_Pbf + (size_t)r * DDIM; }
    float4 v = reinterpret_cast<const float4*>(src)[lane];
    float ss = v.x * v.x + v.y * v.y + v.z * v.z + v.w * v.w;
    #pragma unroll
    for (int o = 16; o > 0; o >>= 1) ss += __shfl_xor_sync(0xFFFFFFFFu, ss, o);
    float s = 1.0f / fmaxf(sqrtf(ss), 1e-12f);
    __nv_bfloat162 h0 = __floats2bfloat162_rn(v.x * s, v.y * s);
    __nv_bfloat162 h1 = __floats2bfloat162_rn(v.z * s, v.w * s);
    reinterpret_cast<__nv_bfloat162*>(dst)[lane * 2 + 0] = h0;
    reinterpret_cast<__nv_bfloat162*>(dst)[lane * 2 + 1] = h1;
}

// ============================================================================
// cp.async loader: 128x128 bf16 tile (row-major) -> padded SMEM (272B rows)
// ============================================================================
__device__ __forceinline__ void cp_tile(uint32_t sbase, const __nv_bfloat16* gsrc, int tid) {
    const char* g = reinterpret_cast<const char*>(gsrc);
    #pragma unroll
    for (int i = 0; i < 8; i++) {
        int idx = tid + i * 256;          // 2048 chunks of 16B
        int row = idx >> 4;
        int c   = idx & 15;
        uint32_t s = sbase + row * ROWB + c * 16;
        CP_ASYNC16(s, g + idx * 16);
    }
}

// ============================================================================
// Kernel 2: persistent balanced fused GEMM + exp rowsum + diag.
// grid = 2*SMs workers; jobs j in [0,16384): rb = j>>7, ct = j&127.
// Worker w owns jobs [w*NJOBS/G, (w+1)*NJOBS/G) -> <=2 row-block segments.
// Per segment: A tile -> slab0, frags to regs, stream B tiles (3-slab
// cp.async rotation, one __syncthreads per tile), flush S via atomicAdd.
// ============================================================================
__global__ void __launch_bounds__(256, 2) infonce_main_kernel() {
    extern __shared__ char smem[];
    uint32_t sb = smem_to_u32(smem);
    int tid = threadIdx.x;
    int lane = tid & 31;
    int w = tid >> 5;
    int wr = w >> 1;            // row-group 0..3 (32 rows)
    int wc = w & 1;             // col-group 0..1 (64 cols)

    int G = gridDim.x;
    int j0 = (int)(((long long)blockIdx.x * NJOBS) / G);
    int j1 = (int)(((long long)(blockIdx.x + 1) * NJOBS) / G);

    int g = lane >> 2;
    int tig = lane & 3;
    uint32_t b_lane_off = (uint32_t)(((lane & 7) + ((lane >> 4) << 3)) * ROWB
                                     + ((lane >> 3) & 1) * 16)
                          + (uint32_t)(wc * 64) * ROWB;
    const uint32_t bufoff[3] = {SLAB, 2 * SLAB, 0};

    int j = j0;
    while (j < j1) {
        int rb = j >> 7;
        int c0 = j & 127;
        int cend = min(j1 - (rb << 7), 128);   // exclusive col-tile end in this rb
        int nt = cend - c0;

        // all warps done with previous segment's smem before overwriting
        __syncthreads();

        // Prologue: A -> slab0; B(c0) -> buf0, B(c0+1) -> buf1
        cp_tile(sb + 0, g_Abf + (size_t)rb * TILE * DDIM, tid);
        CP_COMMIT();
        cp_tile(sb + bufoff[0], g_Pbf + (size_t)c0 * TILE * DDIM, tid);
        CP_COMMIT();
        if (nt > 1)
            cp_tile(sb + bufoff[1], g_Pbf + (size_t)(c0 + 1) * TILE * DDIM, tid);
        CP_COMMIT();
        CP_WAIT2();              // A done (B may still be in flight)
        __syncthreads();

        // A fragments: 8 k-steps x 2 m16-frags x 4 regs
        uint32_t afrag[8][2][4];
        #pragma unroll
        for (int f = 0; f < 2; f++) {
            uint32_t a_addr = sb + (wr * 32 + f * 16 + (lane & 15)) * ROWB + (lane >> 4) * 16;
            #pragma unroll
            for (int k = 0; k < 8; k++)
                LDSM_X4(afrag[k][f][0], afrag[k][f][1], afrag[k][f][2], afrag[k][f][3],
                        a_addr + k * 32);
        }
        // iter-0's barrier orders frag loads before slab0 is reused for B

        float S[4] = {0.f, 0.f, 0.f, 0.f};
        float d[4] = {0.f, 0.f, 0.f, 0.f};
        int curbuf = 0, nxtbuf = 2;

        for (int t = 0; t < nt; t++) {
            CP_WAIT1();          // tile t complete (t+1 may pend)
            __syncthreads();
            if (t + 2 < nt)
                cp_tile(sb + bufoff[nxtbuf], g_Pbf + (size_t)(c0 + t + 2) * TILE * DDIM, tid);
            CP_COMMIT();         // keep group counts aligned (empty ok)

            uint32_t bbase = sb + bufoff[curbuf] + b_lane_off;
            int diag_t = (c0 + t == rb);

            #pragma unroll
            for (int c = 0; c < 4; c++) {
                float acc[2][2][4];
                #pragma unroll
                for (int f = 0; f < 2; f++)
                    #pragma unroll
                    for (int nb = 0; nb < 2; nb++)
                        #pragma unroll
                        for (int q = 0; q < 4; q++) acc[f][nb][q] = 0.0f;

                uint32_t bchunk = bbase + (uint32_t)(c * 16) * ROWB;
                #pragma unroll
                for (int k = 0; k < 8; k++) {
                    uint32_t b0, b1, b2, b3;
                    LDSM_X4(b0, b1, b2, b3, bchunk + k * 32);
                    MMA_BF16(acc[0][0], afrag[k][0], b0, b1);
                    MMA_BF16(acc[0][1], afrag[k][0], b2, b3);
                    MMA_BF16(acc[1][0], afrag[k][1], b0, b1);
                    MMA_BF16(acc[1][1], afrag[k][1], b2, b3);
                }
                #pragma unroll
                for (int f = 0; f < 2; f++) {
                    #pragma unroll
                    for (int nb = 0; nb < 2; nb++) {
                        #pragma unroll
                        for (int q = 0; q < 4; q++) {
                            float v = acc[f][nb][q];
                            int hi = q >> 1;
                            S[f * 2 + hi] += ex2f_fast(v * C_EXP);
                            if (diag_t) {
                                int col_local = wc * 64 + c * 16 + nb * 8 + tig * 2 + (q & 1);
                                int row_local = wr * 32 + f * 16 + hi * 8 + g;
                                if (col_local == row_local) d[f * 2 + hi] = v;
                            }
                        }
                    }
                }
            }
            if (++curbuf == 3) curbuf = 0;
            if (++nxtbuf == 3) nxtbuf = 0;
        }

        // flush: reduce across the 4 threads sharing each row, then atomics
        #pragma unroll
        for (int i = 0; i < 4; i++) {
            S[i] += __shfl_xor_sync(0xFFFFFFFFu, S[i], 1);
            S[i] += __shfl_xor_sync(0xFFFFFFFFu, S[i], 2);
            d[i] += __shfl_xor_sync(0xFFFFFFFFu, d[i], 1);
            d[i] += __shfl_xor_sync(0xFFFFFFFFu, d[i], 2);
        }
        if (tig == 0) {
            int seg_has_diag = (rb >= c0) && (rb < cend);
            int wrote_diag = seg_has_diag && ((wr >> 1) == wc);
            #pragma unroll
            for (int i = 0; i < 4; i++) {
                int row_local = wr * 32 + (i >> 1) * 16 + (i & 1) * 8 + g;
                int row = rb * TILE + row_local;
                atomicAdd(&g_partS[row], S[i]);
                if (wrote_diag) g_diagv[row] = d[i];
            }
        }
        j += nt;
    }
}

// ============================================================================
// Kernel 3: per-row loss + global reduction
// ============================================================================
__global__ void __launch_bounds__(256) rowsum_kernel() {
    int row = blockIdx.x * 256 + threadIdx.x;
    float v = logf(g_partS[row]) - g_diagv[row] * INV_T;
    #pragma unroll
    for (int o = 16; o > 0; o >>= 1) v += __shfl_xor_sync(0xFFFFFFFFu, v, o);
    __shared__ float red[8];
    int lane = threadIdx.x & 31, wid = threadIdx.x >> 5;
    if (lane == 0) red[wid] = v;
    __syncthreads();
    if (wid == 0) {
        float s = (lane < 8) ? red[lane] : 0.0f;
        #pragma unroll
        for (int o = 4; o > 0; o >>= 1) s += __shfl_xor_sync(0xFFFFFFFFu, s, o);
        if (lane == 0) atomicAdd(&g_acc, s);
    }
}

// ============================================================================
// Kernel 4: finalize
// ============================================================================
__global__ void finalize_kernel(float* out) {
    out[0] = g_acc * (1.0f / (float)NROWS);
}

// ============================================================================
// Launch
// ============================================================================
extern "C" void kernel_launch(void* const* d_in, const int* in_sizes, int n_in,
                              void* d_out, int out_size) {
    const float* A = (const float*)d_in[0];
    const float* P = (const float*)d_in[1];
    int nsm = 148;
    cudaDeviceGetAttribute(&nsm, cudaDevAttrMultiProcessorCount, 0);
    cudaFuncSetAttribute(infonce_main_kernel,
                         cudaFuncAttributeMaxDynamicSharedMemorySize, SMEM_TOTAL);
    normalize_kernel<<<(2 * NROWS) / 8, 256>>>(A, P);
    infonce_main_kernel<<<2 * nsm, 256, SMEM_TOTAL>>>();
    rowsum_kernel<<<NROWS / 256, 256>>>();
    finalize_kernel<<<1, 1>>>((float*)d_out);
}